// round 5
// baseline (speedup 1.0000x reference)
#include <cuda_runtime.h>
#include <cstdint>
#include <cstddef>

#define DEV_INLINE __device__ __forceinline__

// ---------------- problem constants ----------------
constexpr int NB = 8, CIN = 512, COUT = 512, RES = 64, WDIM = 512;
constexpr int WP = 66;                 // padded spatial dim
constexpr int PLANE = WP * WP;         // 4356
constexpr int GPT = NB * PLANE;        // 34848 padded pixels total
constexpr int XMARG = 384;             // margin rows each side of g_xpad
constexpr int XROWS = GPT + 2 * XMARG; // 35616

// ---------------- GEMM tiling ----------------
constexpr int BM = 256, BN = 128, KC = 32;
constexpr int NCH = CIN / KC;           // 16 ci-chunks
constexpr int MT = (GPT + BM - 1) / BM; // 137
constexpr int NT = COUT / BN;           // 4
constexpr int NIT = NCH * 9;            // 144 (kc,tap) iterations
constexpr int STRIP_ROWS = BM + 134;    // 390
constexpr int SSTR = 36;                // strip/B row stride in floats
constexpr int NTHR = 512;

// ---------------- smem layout (bytes) ----------------
constexpr int STRIP_BYTES = STRIP_ROWS * SSTR * 4;     // 56160
constexpr int SO_S0 = 0;
constexpr int SO_S1 = 56192;
constexpr int SO_B0 = 112384;                          // 3 B buffers, 18432 each
constexpr int BBYTES = 128 * SSTR * 4;                 // 18432
constexpr int SMEM_TOTAL = SO_B0 + 3 * BBYTES;         // 167680

// ---------------- device scratch (allocation is forbidden) ----------------
__device__ __align__(128) float g_style[NB * CIN];
__device__ __align__(128) float g_xpad[(size_t)XROWS * CIN];  // [row][ci]
__device__ __align__(128) float g_wtap[9 * COUT * CIN];       // [tap][co][ci]

// ---------------- PTX helpers (sm_80 baseline only) ----------------
DEV_INLINE uint32_t smem_u32(const void* p) {
    uint32_t a;
    asm("{ .reg .u64 t; cvta.to.shared.u64 t, %1; cvt.u32.u64 %0, t; }"
        : "=r"(a) : "l"(p));
    return a;
}

DEV_INLINE float tf32_rna(float v) {
    uint32_t t;
    asm("cvt.rna.tf32.f32 %0, %1;" : "=r"(t) : "f"(v));
    return __uint_as_float(t);
}

DEV_INLINE void cp_async16(uint32_t dst, const void* src) {
    asm volatile("cp.async.ca.shared.global [%0], [%1], 16;"
                 :: "r"(dst), "l"(src) : "memory");
}
DEV_INLINE void cp_commit() {
    asm volatile("cp.async.commit_group;" ::: "memory");
}
template <int N> DEV_INLINE void cp_wait() {
    asm volatile("cp.async.wait_group %0;" :: "n"(N) : "memory");
}

DEV_INLINE void mma_tf32(float* c, const uint32_t* a, const uint32_t* b) {
    asm volatile(
        "mma.sync.aligned.m16n8k8.row.col.f32.tf32.tf32.f32 "
        "{%0,%1,%2,%3}, {%4,%5,%6,%7}, {%8,%9}, {%0,%1,%2,%3};"
        : "+f"(c[0]), "+f"(c[1]), "+f"(c[2]), "+f"(c[3])
        : "r"(a[0]), "r"(a[1]), "r"(a[2]), "r"(a[3]),
          "r"(b[0]), "r"(b[1]));
}

// ============================================================================
// Kernel 1: style[b][ci] = w[b,:] . affine_w[ci,:] + affine_b[ci]
// ============================================================================
__global__ void k_style(const float* __restrict__ w,
                        const float* __restrict__ aw,
                        const float* __restrict__ ab) {
    int gw = (blockIdx.x * blockDim.x + threadIdx.x) >> 5;
    int lane = threadIdx.x & 31;
    if (gw >= NB * CIN) return;
    int b = gw >> 9;
    int ci = gw & (CIN - 1);
    const float* wr = w + b * WDIM;
    const float* ar = aw + ci * WDIM;
    float s = 0.f;
    for (int d = lane; d < WDIM; d += 32) s += wr[d] * ar[d];
    #pragma unroll
    for (int o = 16; o; o >>= 1) s += __shfl_xor_sync(0xFFFFFFFFu, s, o);
    if (lane == 0) g_style[b * CIN + ci] = s + ab[ci];
}

// ============================================================================
// Kernel 2: g_wtap[tap][co][ci] = tf32(weight[co][ci][tap])
// ============================================================================
__global__ void k_wprep(const float* __restrict__ wt) {
    int idx = blockIdx.x * 256 + threadIdx.x;   // co*CIN + ci
    if (idx >= COUT * CIN) return;
    const float* src = wt + (size_t)idx * 9;
    #pragma unroll
    for (int tp = 0; tp < 9; tp++)
        g_wtap[tp * (COUT * CIN) + idx] = tf32_rna(src[tp]);
}

// ============================================================================
// Kernel 3: zero margins + zero-padding borders of g_xpad
// ============================================================================
__global__ void k_zero() {
    int row = (int)blockIdx.x - XMARG;
    bool z;
    if (row < 0 || row >= GPT) z = true;
    else {
        int rem = row % PLANE;
        int py = rem / WP, px = rem % WP;
        z = (py == 0) || (py == WP - 1) || (px == 0) || (px == WP - 1);
    }
    if (!z) return;
    float4* dst = (float4*)(g_xpad + (size_t)(row + XMARG) * CIN);
    dst[threadIdx.x] = make_float4(0.f, 0.f, 0.f, 0.f);
}

// ============================================================================
// Kernel 4: g_xpad[gp][ci] = tf32( x[b,ci,py-1,px-1] * style[b,ci] )
// ============================================================================
__global__ void k_xprep(const float* __restrict__ x) {
    __shared__ float tile[32 * 65];
    __shared__ float sstyle[32];
    int cib = blockIdx.x * 32;
    int py  = blockIdx.y + 1;          // padded row 1..64
    int b   = blockIdx.z;
    int t   = threadIdx.x;
    if (t < 32) sstyle[t] = g_style[b * CIN + cib + t];
    int i = t >> 3, j = t & 7;
    const float* srow = x + (((size_t)(b * CIN + cib + i) * RES + (py - 1)) * RES);
    float4 v0 = ((const float4*)srow)[j * 2];
    float4 v1 = ((const float4*)srow)[j * 2 + 1];
    int c = j * 8;
    tile[i * 65 + c + 0] = v0.x; tile[i * 65 + c + 1] = v0.y;
    tile[i * 65 + c + 2] = v0.z; tile[i * 65 + c + 3] = v0.w;
    tile[i * 65 + c + 4] = v1.x; tile[i * 65 + c + 5] = v1.y;
    tile[i * 65 + c + 6] = v1.z; tile[i * 65 + c + 7] = v1.w;
    __syncthreads();
    int wrp = t >> 5, l = t & 31;
    float st = sstyle[l];
    size_t rowbase = (size_t)XMARG + (size_t)b * PLANE + (size_t)py * WP;
    #pragma unroll
    for (int pp = 0; pp < 8; pp++) {
        int px = wrp * 8 + pp;
        float v = tile[l * 65 + px] * st;
        g_xpad[(rowbase + px + 1) * CIN + cib + l] = tf32_rna(v);
    }
}

// ============================================================================
// Kernel 5: implicit-GEMM conv, mma.sync tf32, deep cp.async pipeline.
// BM=256 x BN=128, 512 threads (16 warps 4m x 4n), 1 CTA/SM.
//  - B (weights): 3 buffers, committed 2 iterations ahead.
//  - strip (x):   2 buffers, next chunk issued at tap0, stays outstanding.
// ============================================================================
__global__ __launch_bounds__(NTHR, 1) void k_gemm(const float* __restrict__ bias,
                                                  float* __restrict__ out) {
    extern __shared__ __align__(128) char smem[];
    const int t = threadIdx.x;
    const int wid = t >> 5;
    const int lane = t & 31;
    const int g = lane >> 2;          // 0..7
    const int tg = lane & 3;          // 0..3
    const int wm = wid >> 2;          // 0..3  (m warp coord, 64 rows each)
    const int wn = wid & 3;           // 0..3  (n warp coord, 32 cols each)
    const int n0 = blockIdx.x * BN;
    const int gp0 = (int)blockIdx.y * BM;

    uint32_t sbase = smem_u32(smem);

    float c[4][4][4];
    #pragma unroll
    for (int mi = 0; mi < 4; mi++)
        #pragma unroll
        for (int ni = 0; ni < 4; ni++)
            #pragma unroll
            for (int q = 0; q < 4; q++) c[mi][ni][q] = 0.f;

    const float* xsrc = g_xpad + (size_t)(XMARG + gp0 - 67) * CIN;

    // per-thread frag base offsets (in floats)
    const int a_off = (wm * 64 + g) * SSTR + tg;
    const int b_off = (wn * 32 + g) * SSTR + tg;

    // ---- strip issue helper (chunk kc -> buffer kc&1) ----
    auto issue_strip = [&](int kc) {
        const float* src = xsrc + kc * KC;
        uint32_t dst = sbase + ((kc & 1) ? SO_S1 : SO_S0);
        #pragma unroll
        for (int k = 0; k < 7; k++) {
            int idx = t + k * NTHR;
            if (idx < STRIP_ROWS * 8) {
                int r = idx >> 3, j = idx & 7;
                cp_async16(dst + (r * SSTR + j * 4) * 4,
                           src + (size_t)r * CIN + j * 4);
            }
        }
        cp_commit();
    };
    // ---- B issue helper (iteration index -> buffer it%3) ----
    auto issue_b = [&](int it) {
        int kc = it / 9, tap = it - kc * 9;
        const float* wsrc = g_wtap + ((size_t)tap * COUT + n0) * CIN + kc * KC;
        uint32_t dst = sbase + SO_B0 + (it % 3) * BBYTES;
        #pragma unroll
        for (int k = 0; k < 2; k++) {
            int idx = t + k * NTHR;
            int r = idx >> 3, j = idx & 7;
            cp_async16(dst + (r * SSTR + j * 4) * 4,
                       wsrc + (size_t)r * CIN + j * 4);
        }
        cp_commit();
    };

    // ---- prologue: groups S(0), B(0), B(1) ----
    issue_strip(0);
    issue_b(0);
    issue_b(1);

    for (int it = 0; it < NIT; it++) {
        const int kc = it / 9;
        const int tap = it - kc * 9;

        // ---- wait for B(it) and S(kc); leave newer groups in flight ----
        // newer-than-B(it): B(it+1) (if exists) + S committed at iter it-1/it-2
        {
            int newer = (it + 1 < NIT) ? 1 : 0;
            int p1 = it - 1, p2 = it - 2;
            bool s_newer =
                (p1 >= 0 && p1 % 9 == 0 && p1 / 9 + 1 < NCH) ||
                (p2 >= 0 && p2 % 9 == 0 && p2 / 9 + 1 < NCH);
            if (s_newer) newer++;
            if (newer >= 2)      cp_wait<2>();
            else if (newer == 1) cp_wait<1>();
            else                 cp_wait<0>();
        }
        __syncthreads();

        // ---- commits for the future (write buffers freed by sync above) ----
        if (it + 2 < NIT) issue_b(it + 2);
        if (tap == 0 && kc + 1 < NCH) issue_strip(kc + 1);

        // ---- compute: tap shift is a pure strip-row offset ----
        const int srow0 = (tap / 3) * WP + (tap % 3);
        const float* stripf =
            (const float*)(smem + ((kc & 1) ? SO_S1 : SO_S0));
        const uint32_t* ab =
            (const uint32_t*)(stripf + srow0 * SSTR + a_off);
        const uint32_t* bb =
            (const uint32_t*)(smem + SO_B0 + (it % 3) * BBYTES) + b_off;

        #pragma unroll
        for (int ks = 0; ks < 4; ks++) {
            uint32_t A[4][4];
            #pragma unroll
            for (int mi = 0; mi < 4; mi++) {
                const uint32_t* ap = ab + mi * (16 * SSTR) + ks * 8;
                A[mi][0] = ap[0];
                A[mi][1] = ap[8 * SSTR];
                A[mi][2] = ap[4];
                A[mi][3] = ap[8 * SSTR + 4];
            }
            uint32_t B[4][2];
            #pragma unroll
            for (int ni = 0; ni < 4; ni++) {
                const uint32_t* bp = bb + ni * (8 * SSTR) + ks * 8;
                B[ni][0] = bp[0];
                B[ni][1] = bp[4];
            }
            #pragma unroll
            for (int mi = 0; mi < 4; mi++)
                #pragma unroll
                for (int ni = 0; ni < 4; ni++)
                    mma_tf32(c[mi][ni], A[mi], B[ni]);
        }
    }

    // ---- epilogue: c[mi][ni] rows (g, g+8), cols (2tg, 2tg+1) ----
    #pragma unroll
    for (int mi = 0; mi < 4; mi++) {
        #pragma unroll
        for (int half = 0; half < 2; half++) {
            int mloc = wm * 64 + mi * 16 + half * 8 + g;
            int gp = gp0 + mloc;
            if (gp >= GPT) continue;
            int b = gp / PLANE;
            int rem = gp - b * PLANE;
            int py = rem / WP, px = rem - py * WP;
            if (py < 1 || py > RES || px < 1 || px > RES) continue;
            size_t obase =
                (((size_t)b * COUT) * RES + (py - 1)) * RES + (px - 1);
            #pragma unroll
            for (int ni = 0; ni < 4; ni++) {
                #pragma unroll
                for (int j = 0; j < 2; j++) {
                    int co = n0 + wn * 32 + ni * 8 + 2 * tg + j;
                    out[obase + (size_t)co * (RES * RES)] =
                        c[mi][ni][half * 2 + j] + __ldg(&bias[co]);
                }
            }
        }
    }
}

// ============================================================================
// launch
// ============================================================================
extern "C" void kernel_launch(void* const* d_in, const int* in_sizes, int n_in,
                              void* d_out, int out_size) {
    const float* x   = (const float*)d_in[0];
    const float* w   = (const float*)d_in[1];
    const float* wt  = (const float*)d_in[2];
    const float* bia = (const float*)d_in[3];
    const float* aw  = (const float*)d_in[4];
    const float* ab  = (const float*)d_in[5];
    float* out = (float*)d_out;

    cudaFuncSetAttribute(k_gemm, cudaFuncAttributeMaxDynamicSharedMemorySize,
                         SMEM_TOTAL);

    k_style<<<(NB * CIN * 32 + 255) / 256, 256>>>(w, aw, ab);
    k_wprep<<<(COUT * CIN + 255) / 256, 256>>>(wt);
    k_zero<<<XROWS, 128>>>();
    k_xprep<<<dim3(CIN / 32, RES, NB), 256>>>(x);
    k_gemm<<<dim3(NT, MT), 512, SMEM_TOTAL>>>(bia, out);
}

// round 9
// speedup vs baseline: 1.0357x; 1.0357x over previous
#include <cuda_runtime.h>
#include <cstdint>
#include <cstddef>

#define DEV_INLINE __device__ __forceinline__

// ---------------- problem constants ----------------
constexpr int NB = 8, CIN = 512, COUT = 512, RES = 64, WDIM = 512;
constexpr int WP = 66;                 // padded spatial dim
constexpr int PLANE = WP * WP;         // 4356
constexpr int GPT = NB * PLANE;        // 34848 padded pixels total
constexpr int XMARG = 256;             // margin rows each side of g_xpad
constexpr int XROWS = GPT + 2 * XMARG; // 35360

// ---------------- GEMM tiling ----------------
constexpr int BM = 128, BN = 128, KC = 32;
constexpr int NCH = CIN / KC;           // 16 ci-chunks
constexpr int MT = (GPT + BM - 1) / BM; // 273
constexpr int NT = COUT / BN;           // 4
constexpr int NIT = NCH * 9;            // 144 (kc,tap) iterations
constexpr int STRIP_ROWS = BM + 134;    // 262
constexpr int SSTR = 36;                // strip/B row stride in floats
constexpr int NTHR = 256;

// ---------------- smem layout (bytes) ----------------
constexpr int STRIP_BYTES = STRIP_ROWS * SSTR * 4;  // 37728
constexpr int BBYTES = 128 * SSTR * 4;              // 18432
constexpr int SO_S0 = 0;
constexpr int SO_S1 = 37760;
constexpr int SO_B0 = 75520;
constexpr int SO_B1 = 93952;
constexpr int SMEM_TOTAL = SO_B1 + BBYTES;          // 112384 -> 2 CTAs/SM

// ---------------- device scratch (allocation is forbidden) ----------------
__device__ __align__(128) float g_style[NB * CIN];
__device__ __align__(128) float g_xpad[(size_t)XROWS * CIN];  // [row][ci]
__device__ __align__(128) float g_wtap[9 * COUT * CIN];       // [tap][co][ci]

// ---------------- PTX helpers (sm_80 baseline only) ----------------
DEV_INLINE uint32_t smem_u32(const void* p) {
    uint32_t a;
    asm("{ .reg .u64 t; cvta.to.shared.u64 t, %1; cvt.u32.u64 %0, t; }"
        : "=r"(a) : "l"(p));
    return a;
}

DEV_INLINE float tf32_rna(float v) {
    uint32_t t;
    asm("cvt.rna.tf32.f32 %0, %1;" : "=r"(t) : "f"(v));
    return __uint_as_float(t);
}

DEV_INLINE void cp_async16(uint32_t dst, const void* src) {
    asm volatile("cp.async.ca.shared.global [%0], [%1], 16;"
                 :: "r"(dst), "l"(src) : "memory");
}
DEV_INLINE void cp_commit() {
    asm volatile("cp.async.commit_group;" ::: "memory");
}
template <int N> DEV_INLINE void cp_wait() {
    asm volatile("cp.async.wait_group %0;" :: "n"(N) : "memory");
}

DEV_INLINE void mma_tf32(float* c, const uint32_t* a, const uint32_t* b) {
    asm volatile(
        "mma.sync.aligned.m16n8k8.row.col.f32.tf32.tf32.f32 "
        "{%0,%1,%2,%3}, {%4,%5,%6,%7}, {%8,%9}, {%0,%1,%2,%3};"
        : "+f"(c[0]), "+f"(c[1]), "+f"(c[2]), "+f"(c[3])
        : "r"(a[0]), "r"(a[1]), "r"(a[2]), "r"(a[3]),
          "r"(b[0]), "r"(b[1]));
}

// ============================================================================
// Kernel 1: style[b][ci] = w[b,:] . affine_w[ci,:] + affine_b[ci]
// ============================================================================
__global__ void k_style(const float* __restrict__ w,
                        const float* __restrict__ aw,
                        const float* __restrict__ ab) {
    int gw = (blockIdx.x * blockDim.x + threadIdx.x) >> 5;
    int lane = threadIdx.x & 31;
    if (gw >= NB * CIN) return;
    int b = gw >> 9;
    int ci = gw & (CIN - 1);
    const float* wr = w + b * WDIM;
    const float* ar = aw + ci * WDIM;
    float s = 0.f;
    for (int d = lane; d < WDIM; d += 32) s += wr[d] * ar[d];
    #pragma unroll
    for (int o = 16; o; o >>= 1) s += __shfl_xor_sync(0xFFFFFFFFu, s, o);
    if (lane == 0) g_style[b * CIN + ci] = s + ab[ci];
}

// ============================================================================
// Kernel 2: g_wtap[tap][co][ci] = tf32(weight[co][ci][tap])
// ============================================================================
__global__ void k_wprep(const float* __restrict__ wt) {
    int idx = blockIdx.x * 256 + threadIdx.x;   // co*CIN + ci
    if (idx >= COUT * CIN) return;
    const float* src = wt + (size_t)idx * 9;
    #pragma unroll
    for (int tp = 0; tp < 9; tp++)
        g_wtap[tp * (COUT * CIN) + idx] = tf32_rna(src[tp]);
}

// ============================================================================
// Kernel 3: zero margins + zero-padding borders of g_xpad
// ============================================================================
__global__ void k_zero() {
    int row = (int)blockIdx.x - XMARG;
    bool z;
    if (row < 0 || row >= GPT) z = true;
    else {
        int rem = row % PLANE;
        int py = rem / WP, px = rem % WP;
        z = (py == 0) || (py == WP - 1) || (px == 0) || (px == WP - 1);
    }
    if (!z) return;
    float4* dst = (float4*)(g_xpad + (size_t)(row + XMARG) * CIN);
    dst[threadIdx.x] = make_float4(0.f, 0.f, 0.f, 0.f);
}

// ============================================================================
// Kernel 4: g_xpad[gp][ci] = tf32( x[b,ci,py-1,px-1] * style[b,ci] )
// ============================================================================
__global__ void k_xprep(const float* __restrict__ x) {
    __shared__ float tile[32 * 65];
    __shared__ float sstyle[32];
    int cib = blockIdx.x * 32;
    int py  = blockIdx.y + 1;          // padded row 1..64
    int b   = blockIdx.z;
    int t   = threadIdx.x;
    if (t < 32) sstyle[t] = g_style[b * CIN + cib + t];
    int i = t >> 3, j = t & 7;
    const float* srow = x + (((size_t)(b * CIN + cib + i) * RES + (py - 1)) * RES);
    float4 v0 = ((const float4*)srow)[j * 2];
    float4 v1 = ((const float4*)srow)[j * 2 + 1];
    int c = j * 8;
    tile[i * 65 + c + 0] = v0.x; tile[i * 65 + c + 1] = v0.y;
    tile[i * 65 + c + 2] = v0.z; tile[i * 65 + c + 3] = v0.w;
    tile[i * 65 + c + 4] = v1.x; tile[i * 65 + c + 5] = v1.y;
    tile[i * 65 + c + 6] = v1.z; tile[i * 65 + c + 7] = v1.w;
    __syncthreads();
    int wrp = t >> 5, l = t & 31;
    float st = sstyle[l];
    size_t rowbase = (size_t)XMARG + (size_t)b * PLANE + (size_t)py * WP;
    #pragma unroll
    for (int pp = 0; pp < 8; pp++) {
        int px = wrp * 8 + pp;
        float v = tile[l * 65 + px] * st;
        g_xpad[(rowbase + px + 1) * CIN + cib + l] = tf32_rna(v);
    }
}

// ============================================================================
// Kernel 5: implicit-GEMM conv, mma.sync tf32, fully covered cp.async pipeline
// BM=128 x BN=128, 256 threads (8 warps 2m x 4n), 2 CTAs/SM.
//  - strip (x): 2 buffers; strip(kc+1) committed at tap==7 (~2 iters cover)
//  - B (wt):    2 buffers; B(it+1) committed right after barrier (1 iter cover)
//  - waits: wait_group<1> at tap==8 (leave strip in flight), else <0>;
//    exactly ONE __syncthreads per iteration.
// ============================================================================
__global__ __launch_bounds__(NTHR, 2) void k_gemm(const float* __restrict__ bias,
                                                  float* __restrict__ out) {
    extern __shared__ __align__(128) char smem[];
    const int t = threadIdx.x;
    const int wid = t >> 5;
    const int lane = t & 31;
    const int g = lane >> 2;          // 0..7
    const int tg = lane & 3;          // 0..3
    const int wm = wid >> 2;          // 0..1  (m warp coord, 64 rows each)
    const int wn = wid & 3;           // 0..3  (n warp coord, 32 cols each)
    const int n0 = blockIdx.x * BN;
    const int gp0 = (int)blockIdx.y * BM;

    uint32_t sbase = smem_u32(smem);

    float c[4][4][4];
    #pragma unroll
    for (int mi = 0; mi < 4; mi++)
        #pragma unroll
        for (int ni = 0; ni < 4; ni++)
            #pragma unroll
            for (int q = 0; q < 4; q++) c[mi][ni][q] = 0.f;

    const float* xsrc = g_xpad + (size_t)(XMARG + gp0 - 67) * CIN;

    // per-thread frag base offsets (in floats)
    const int a_off = (wm * 64 + g) * SSTR + tg;
    const int b_off = (wn * 32 + g) * SSTR + tg;

    auto issue_strip = [&](int kc) {
        const float* src = xsrc + kc * KC;
        uint32_t dst = sbase + ((kc & 1) ? SO_S1 : SO_S0);
        #pragma unroll
        for (int k = 0; k < 9; k++) {
            int idx = t + k * NTHR;
            if (idx < STRIP_ROWS * 8) {
                int r = idx >> 3, j = idx & 7;
                cp_async16(dst + (r * SSTR + j * 4) * 4,
                           src + (size_t)r * CIN + j * 4);
            }
        }
        cp_commit();
    };
    auto issue_b = [&](int it) {
        int kc = it / 9, tap = it - kc * 9;
        const float* wsrc = g_wtap + ((size_t)tap * COUT + n0) * CIN + kc * KC;
        uint32_t dst = sbase + ((it & 1) ? SO_B1 : SO_B0);
        #pragma unroll
        for (int k = 0; k < 4; k++) {
            int idx = t + k * NTHR;
            int r = idx >> 3, j = idx & 7;
            cp_async16(dst + (r * SSTR + j * 4) * 4,
                       wsrc + (size_t)r * CIN + j * 4);
        }
        cp_commit();
    };

    // ---- prologue: groups S(0), B(0) ----
    issue_strip(0);
    issue_b(0);

    for (int it = 0; it < NIT; it++) {
        const int kc = it / 9;
        const int tap = it - kc * 9;

        // Outstanding (oldest->newest) at this point:
        //   tap==8:        [B(it), S(kc+1)]           -> wait<1> (B done, S flies)
        //   tap==0 (kc>0): [S(kc), B(it)]             -> wait<0> (need both)
        //   otherwise:     [B(it)]                    -> wait<0>
        if (tap == 8 && kc + 1 < NCH) cp_wait<1>(); else cp_wait<0>();
        __syncthreads();   // all warps past iter it-1 compute; buffers consistent

        // refills into buffers freed by the barrier above
        if (it + 1 < NIT) issue_b(it + 1);                 // buffer (it+1)&1
        if (tap == 7 && kc + 1 < NCH) issue_strip(kc + 1); // buffer (kc+1)&1

        // ---- compute: tap shift is a pure strip-row offset ----
        const int srow0 = (tap / 3) * WP + (tap % 3);
        const float* stripf = (const float*)(smem + ((kc & 1) ? SO_S1 : SO_S0));
        const uint32_t* ab = (const uint32_t*)(stripf + srow0 * SSTR + a_off);
        const uint32_t* bb =
            (const uint32_t*)(smem + ((it & 1) ? SO_B1 : SO_B0)) + b_off;

        #pragma unroll
        for (int ks = 0; ks < 4; ks++) {
            uint32_t A[4][4];
            #pragma unroll
            for (int mi = 0; mi < 4; mi++) {
                const uint32_t* ap = ab + mi * (16 * SSTR) + ks * 8;
                A[mi][0] = ap[0];
                A[mi][1] = ap[8 * SSTR];
                A[mi][2] = ap[4];
                A[mi][3] = ap[8 * SSTR + 4];
            }
            uint32_t B[4][2];
            #pragma unroll
            for (int ni = 0; ni < 4; ni++) {
                const uint32_t* bp = bb + ni * (8 * SSTR) + ks * 8;
                B[ni][0] = bp[0];
                B[ni][1] = bp[4];
            }
            #pragma unroll
            for (int mi = 0; mi < 4; mi++)
                #pragma unroll
                for (int ni = 0; ni < 4; ni++)
                    mma_tf32(c[mi][ni], A[mi], B[ni]);
        }
    }

    // ---- epilogue: c[mi][ni] rows (g, g+8), cols (2tg, 2tg+1) ----
    #pragma unroll
    for (int mi = 0; mi < 4; mi++) {
        #pragma unroll
        for (int half = 0; half < 2; half++) {
            int mloc = wm * 64 + mi * 16 + half * 8 + g;
            int gp = gp0 + mloc;
            if (gp >= GPT) continue;
            int b = gp / PLANE;
            int rem = gp - b * PLANE;
            int py = rem / WP, px = rem - py * WP;
            if (py < 1 || py > RES || px < 1 || px > RES) continue;
            size_t obase =
                (((size_t)b * COUT) * RES + (py - 1)) * RES + (px - 1);
            #pragma unroll
            for (int ni = 0; ni < 4; ni++) {
                #pragma unroll
                for (int j = 0; j < 2; j++) {
                    int co = n0 + wn * 32 + ni * 8 + 2 * tg + j;
                    out[obase + (size_t)co * (RES * RES)] =
                        c[mi][ni][half * 2 + j] + __ldg(&bias[co]);
                }
            }
        }
    }
}

// ============================================================================
// launch
// ============================================================================
extern "C" void kernel_launch(void* const* d_in, const int* in_sizes, int n_in,
                              void* d_out, int out_size) {
    const float* x   = (const float*)d_in[0];
    const float* w   = (const float*)d_in[1];
    const float* wt  = (const float*)d_in[2];
    const float* bia = (const float*)d_in[3];
    const float* aw  = (const float*)d_in[4];
    const float* ab  = (const float*)d_in[5];
    float* out = (float*)d_out;

    cudaFuncSetAttribute(k_gemm, cudaFuncAttributeMaxDynamicSharedMemorySize,
                         SMEM_TOTAL);

    k_style<<<(NB * CIN * 32 + 255) / 256, 256>>>(w, aw, ab);
    k_wprep<<<(COUT * CIN + 255) / 256, 256>>>(wt);
    k_zero<<<XROWS, 128>>>();
    k_xprep<<<dim3(CIN / 32, RES, NB), 256>>>(x);
    k_gemm<<<dim3(NT, MT), NTHR, SMEM_TOTAL>>>(bia, out);
}

// round 10
// speedup vs baseline: 1.6818x; 1.6239x over previous
#include <cuda_runtime.h>
#include <cuda_fp16.h>
#include <cstdint>
#include <cstddef>

#define DEV_INLINE __device__ __forceinline__

// ---------------- problem constants ----------------
constexpr int NB = 8, CIN = 512, COUT = 512, RES = 64, WDIM = 512;
constexpr int WP = 66;                 // padded spatial dim
constexpr int PLANE = WP * WP;         // 4356
constexpr int GPT = NB * PLANE;        // 34848 padded pixels total
constexpr int XMARG = 256;             // margin rows each side of g_xpad
constexpr int XROWS = GPT + 2 * XMARG; // 35360

// ---------------- GEMM tiling ----------------
constexpr int BM = 128, BN = 128, KC = 32;   // 32 ci per chunk
constexpr int NCH = CIN / KC;           // 16 ci-chunks
constexpr int MT = (GPT + BM - 1) / BM; // 273
constexpr int NT = COUT / BN;           // 4
constexpr int NIT = NCH * 9;            // 144 (kc,tap) iterations
constexpr int STRIP_ROWS = BM + 134;    // 262
constexpr int NTHR = 256;

// fp16 rows: 32 ci = 64 B data, padded to 80 B (20 words) -> conflict-free
// frag pattern: bank(20g + tg) is a permutation of 0..31.
constexpr int SRW = 20;                 // strip/B row stride in 32-bit words
constexpr int SRB = SRW * 4;            // 80 bytes

// ---------------- smem layout (bytes) ----------------
constexpr int STRIP_BYTES = STRIP_ROWS * SRB;   // 20960
constexpr int BBYTES = 128 * SRB;               // 10240
constexpr int SO_S0 = 0;
constexpr int SO_S1 = 20992;
constexpr int SO_B0 = 41984;
constexpr int SO_B1 = 52224;
constexpr int SMEM_TOTAL = SO_B1 + BBYTES;      // 62464 -> 2+ CTAs/SM

// ---------------- device scratch (allocation is forbidden) ----------------
__device__ __align__(128) float  g_style[NB * CIN];
__device__ __align__(128) __half g_xpad[(size_t)XROWS * CIN];  // [row][ci]
__device__ __align__(128) __half g_wtap[9 * COUT * CIN];       // [tap][co][ci]

// ---------------- PTX helpers (sm_80 baseline only) ----------------
DEV_INLINE uint32_t smem_u32(const void* p) {
    uint32_t a;
    asm("{ .reg .u64 t; cvta.to.shared.u64 t, %1; cvt.u32.u64 %0, t; }"
        : "=r"(a) : "l"(p));
    return a;
}

DEV_INLINE void cp_async16(uint32_t dst, const void* src) {
    asm volatile("cp.async.ca.shared.global [%0], [%1], 16;"
                 :: "r"(dst), "l"(src) : "memory");
}
DEV_INLINE void cp_commit() {
    asm volatile("cp.async.commit_group;" ::: "memory");
}
template <int N> DEV_INLINE void cp_wait() {
    asm volatile("cp.async.wait_group %0;" :: "n"(N) : "memory");
}

// m16n8k16 fp16 MMA, fp32 accumulate
DEV_INLINE void mma_f16(float* c, const uint32_t* a, const uint32_t* b) {
    asm volatile(
        "mma.sync.aligned.m16n8k16.row.col.f32.f16.f16.f32 "
        "{%0,%1,%2,%3}, {%4,%5,%6,%7}, {%8,%9}, {%0,%1,%2,%3};"
        : "+f"(c[0]), "+f"(c[1]), "+f"(c[2]), "+f"(c[3])
        : "r"(a[0]), "r"(a[1]), "r"(a[2]), "r"(a[3]),
          "r"(b[0]), "r"(b[1]));
}

// ============================================================================
// Kernel 1: style[b][ci] = w[b,:] . affine_w[ci,:] + affine_b[ci]
// ============================================================================
__global__ void k_style(const float* __restrict__ w,
                        const float* __restrict__ aw,
                        const float* __restrict__ ab) {
    int gw = (blockIdx.x * blockDim.x + threadIdx.x) >> 5;
    int lane = threadIdx.x & 31;
    if (gw >= NB * CIN) return;
    int b = gw >> 9;
    int ci = gw & (CIN - 1);
    const float* wr = w + b * WDIM;
    const float* ar = aw + ci * WDIM;
    float s = 0.f;
    for (int d = lane; d < WDIM; d += 32) s += wr[d] * ar[d];
    #pragma unroll
    for (int o = 16; o; o >>= 1) s += __shfl_xor_sync(0xFFFFFFFFu, s, o);
    if (lane == 0) g_style[b * CIN + ci] = s + ab[ci];
}

// ============================================================================
// Kernel 2: g_wtap[tap][co][ci] = fp16(weight[co][ci][tap])
// ============================================================================
__global__ void k_wprep(const float* __restrict__ wt) {
    int idx = blockIdx.x * 256 + threadIdx.x;   // co*CIN + ci
    if (idx >= COUT * CIN) return;
    const float* src = wt + (size_t)idx * 9;
    #pragma unroll
    for (int tp = 0; tp < 9; tp++)
        g_wtap[tp * (COUT * CIN) + idx] = __float2half_rn(src[tp]);
}

// ============================================================================
// Kernel 3: zero margins + zero-padding borders of g_xpad (1 KB per row)
// ============================================================================
__global__ void k_zero() {
    int row = (int)blockIdx.x - XMARG;
    bool z;
    if (row < 0 || row >= GPT) z = true;
    else {
        int rem = row % PLANE;
        int py = rem / WP, px = rem % WP;
        z = (py == 0) || (py == WP - 1) || (px == 0) || (px == WP - 1);
    }
    if (!z) return;
    uint2* dst = (uint2*)(g_xpad + (size_t)(row + XMARG) * CIN);
    dst[threadIdx.x] = make_uint2(0u, 0u);
}

// ============================================================================
// Kernel 4: g_xpad[gp][ci] = fp16( x[b,ci,py-1,px-1] * style[b,ci] )
// ============================================================================
__global__ void k_xprep(const float* __restrict__ x) {
    __shared__ float tile[32 * 65];
    __shared__ float sstyle[32];
    int cib = blockIdx.x * 32;
    int py  = blockIdx.y + 1;          // padded row 1..64
    int b   = blockIdx.z;
    int t   = threadIdx.x;
    if (t < 32) sstyle[t] = g_style[b * CIN + cib + t];
    int i = t >> 3, j = t & 7;
    const float* srow = x + (((size_t)(b * CIN + cib + i) * RES + (py - 1)) * RES);
    float4 v0 = ((const float4*)srow)[j * 2];
    float4 v1 = ((const float4*)srow)[j * 2 + 1];
    int c = j * 8;
    tile[i * 65 + c + 0] = v0.x; tile[i * 65 + c + 1] = v0.y;
    tile[i * 65 + c + 2] = v0.z; tile[i * 65 + c + 3] = v0.w;
    tile[i * 65 + c + 4] = v1.x; tile[i * 65 + c + 5] = v1.y;
    tile[i * 65 + c + 6] = v1.z; tile[i * 65 + c + 7] = v1.w;
    __syncthreads();
    int wrp = t >> 5, l = t & 31;
    float st = sstyle[l];
    size_t rowbase = (size_t)XMARG + (size_t)b * PLANE + (size_t)py * WP;
    #pragma unroll
    for (int pp = 0; pp < 8; pp++) {
        int px = wrp * 8 + pp;
        float v = tile[l * 65 + px] * st;
        g_xpad[(rowbase + px + 1) * CIN + cib + l] = __float2half_rn(v);
    }
}

// ============================================================================
// Kernel 5: implicit-GEMM conv, mma.sync fp16 (m16n8k16), cp.async pipeline.
// BM=128 x BN=128, 256 threads (8 warps 2m x 4n), warp tile 64x32.
// fp16 halves the smem crossbar traffic (prev bottleneck: 1536 cyc/iter/SM).
// ============================================================================
__global__ __launch_bounds__(NTHR, 2) void k_gemm(const float* __restrict__ bias,
                                                  float* __restrict__ out) {
    extern __shared__ __align__(128) char smem[];
    const int t = threadIdx.x;
    const int wid = t >> 5;
    const int lane = t & 31;
    const int g = lane >> 2;          // 0..7
    const int tg = lane & 3;          // 0..3
    const int wm = wid >> 2;          // 0..1  (m warp coord, 64 rows each)
    const int wn = wid & 3;           // 0..3  (n warp coord, 32 cols each)
    const int n0 = blockIdx.x * BN;
    const int gp0 = (int)blockIdx.y * BM;

    uint32_t sbase = smem_u32(smem);

    float c[4][4][4];
    #pragma unroll
    for (int mi = 0; mi < 4; mi++)
        #pragma unroll
        for (int ni = 0; ni < 4; ni++)
            #pragma unroll
            for (int q = 0; q < 4; q++) c[mi][ni][q] = 0.f;

    const __half* xsrc = g_xpad + (size_t)(XMARG + gp0 - 67) * CIN;

    // per-thread frag base offsets (in 32-bit words)
    const int a_off = (wm * 64 + g) * SRW + tg;
    const int b_off = (wn * 32 + g) * SRW + tg;

    auto issue_strip = [&](int kc) {
        const __half* src = xsrc + kc * KC;
        uint32_t dst = sbase + ((kc & 1) ? SO_S1 : SO_S0);
        #pragma unroll
        for (int k = 0; k < 5; k++) {
            int idx = t + k * NTHR;            // 262 rows x 4 chunks = 1048
            if (idx < STRIP_ROWS * 4) {
                int r = idx >> 2, j = idx & 3;
                cp_async16(dst + r * SRB + j * 16,
                           src + (size_t)r * CIN + j * 8);
            }
        }
        cp_commit();
    };
    auto issue_b = [&](int it) {
        int kc = it / 9, tap = it - kc * 9;
        const __half* wsrc = g_wtap + ((size_t)tap * COUT + n0) * CIN + kc * KC;
        uint32_t dst = sbase + ((it & 1) ? SO_B1 : SO_B0);
        #pragma unroll
        for (int k = 0; k < 2; k++) {
            int idx = t + k * NTHR;            // 128 rows x 4 chunks = 512
            int r = idx >> 2, j = idx & 3;
            cp_async16(dst + r * SRB + j * 16,
                       wsrc + (size_t)r * CIN + j * 8);
        }
        cp_commit();
    };

    // ---- prologue: groups S(0), B(0) ----
    issue_strip(0);
    issue_b(0);

    for (int it = 0; it < NIT; it++) {
        const int kc = it / 9;
        const int tap = it - kc * 9;

        // Outstanding (oldest->newest):
        //   tap==8: [B(it), S(kc+1)] -> wait<1>;  else [.., B(it)] -> wait<0>
        if (tap == 8 && kc + 1 < NCH) cp_wait<1>(); else cp_wait<0>();
        __syncthreads();

        if (it + 1 < NIT) issue_b(it + 1);                 // buffer (it+1)&1
        if (tap == 7 && kc + 1 < NCH) issue_strip(kc + 1); // buffer (kc+1)&1

        // ---- compute: tap shift is a pure strip-row offset ----
        const int srow0 = (tap / 3) * WP + (tap % 3);
        const uint32_t* ab =
            (const uint32_t*)(smem + ((kc & 1) ? SO_S1 : SO_S0)) +
            srow0 * SRW + a_off;
        const uint32_t* bb =
            (const uint32_t*)(smem + ((it & 1) ? SO_B1 : SO_B0)) + b_off;

        #pragma unroll
        for (int ks = 0; ks < 2; ks++) {       // K = 2 x 16
            uint32_t A[4][4];
            #pragma unroll
            for (int mi = 0; mi < 4; mi++) {
                const uint32_t* ap = ab + mi * (16 * SRW) + ks * 8;
                A[mi][0] = ap[0];
                A[mi][1] = ap[8 * SRW];
                A[mi][2] = ap[4];
                A[mi][3] = ap[8 * SRW + 4];
            }
            uint32_t B[4][2];
            #pragma unroll
            for (int ni = 0; ni < 4; ni++) {
                const uint32_t* bp = bb + ni * (8 * SRW) + ks * 8;
                B[ni][0] = bp[0];
                B[ni][1] = bp[4];
            }
            #pragma unroll
            for (int mi = 0; mi < 4; mi++)
                #pragma unroll
                for (int ni = 0; ni < 4; ni++)
                    mma_f16(c[mi][ni], A[mi], B[ni]);
        }
    }

    // ---- epilogue: c[mi][ni] rows (g, g+8), cols (2tg, 2tg+1) ----
    #pragma unroll
    for (int mi = 0; mi < 4; mi++) {
        #pragma unroll
        for (int half = 0; half < 2; half++) {
            int mloc = wm * 64 + mi * 16 + half * 8 + g;
            int gp = gp0 + mloc;
            if (gp >= GPT) continue;
            int b = gp / PLANE;
            int rem = gp - b * PLANE;
            int py = rem / WP, px = rem - py * WP;
            if (py < 1 || py > RES || px < 1 || px > RES) continue;
            size_t obase =
                (((size_t)b * COUT) * RES + (py - 1)) * RES + (px - 1);
            #pragma unroll
            for (int ni = 0; ni < 4; ni++) {
                #pragma unroll
                for (int j = 0; j < 2; j++) {
                    int co = n0 + wn * 32 + ni * 8 + 2 * tg + j;
                    out[obase + (size_t)co * (RES * RES)] =
                        c[mi][ni][half * 2 + j] + __ldg(&bias[co]);
                }
            }
        }
    }
}

// ============================================================================
// launch
// ============================================================================
extern "C" void kernel_launch(void* const* d_in, const int* in_sizes, int n_in,
                              void* d_out, int out_size) {
    const float* x   = (const float*)d_in[0];
    const float* w   = (const float*)d_in[1];
    const float* wt  = (const float*)d_in[2];
    const float* bia = (const float*)d_in[3];
    const float* aw  = (const float*)d_in[4];
    const float* ab  = (const float*)d_in[5];
    float* out = (float*)d_out;

    cudaFuncSetAttribute(k_gemm, cudaFuncAttributeMaxDynamicSharedMemorySize,
                         SMEM_TOTAL);

    k_style<<<(NB * CIN * 32 + 255) / 256, 256>>>(w, aw, ab);
    k_wprep<<<(COUT * CIN + 255) / 256, 256>>>(wt);
    k_zero<<<XROWS, 128>>>();
    k_xprep<<<dim3(CIN / 32, RES, NB), 256>>>(x);
    k_gemm<<<dim3(NT, MT), NTHR, SMEM_TOTAL>>>(bia, out);
}

// round 11
// speedup vs baseline: 1.9063x; 1.1335x over previous
#include <cuda_runtime.h>
#include <cuda_fp16.h>
#include <cstdint>
#include <cstddef>

#define DEV_INLINE __device__ __forceinline__

// ---------------- problem constants ----------------
constexpr int NB = 8, CIN = 512, COUT = 512, RES = 64, WDIM = 512;
constexpr int WP = 66;                 // padded spatial dim
constexpr int PLANE = WP * WP;         // 4356
constexpr int GPT = NB * PLANE;        // 34848 padded pixels total
constexpr int XMARG = 256;             // margin rows each side of g_xpad
constexpr int XROWS = GPT + 2 * XMARG; // 35360

// ---------------- GEMM tiling ----------------
constexpr int BM = 128, BN = 128, KC = 32;   // 32 ci per chunk
constexpr int NCH = CIN / KC;           // 16 ci-chunks
constexpr int MT = (GPT + BM - 1) / BM; // 273
constexpr int NT = COUT / BN;           // 4
constexpr int NIT = NCH * 9;            // 144 (kc,tap) iterations
constexpr int STRIP_ROWS = BM + 134;    // 262
constexpr int NTHR = 128;               // 4 warps, each 64x64

// fp16 rows: 32 ci = 64 B data, padded to 80 B (20 words) -> conflict-free
constexpr int SRW = 20;                 // strip/B row stride in 32-bit words
constexpr int SRB = SRW * 4;            // 80 bytes

// ---------------- smem layout (bytes) ----------------
constexpr int STRIP_BYTES = STRIP_ROWS * SRB;   // 20960
constexpr int BBYTES = 128 * SRB;               // 10240
constexpr int SO_S0 = 0;
constexpr int SO_S1 = 20992;
constexpr int SO_B0 = 41984;
constexpr int SO_B1 = 52224;
constexpr int SMEM_TOTAL = SO_B1 + BBYTES;      // 62464

// ---------------- device scratch (allocation is forbidden) ----------------
__device__ __align__(128) float  g_style[NB * CIN];
__device__ __align__(128) __half g_xpad[(size_t)XROWS * CIN];  // [row][ci]
__device__ __align__(128) __half g_wtap[9 * COUT * CIN];       // [tap][co][ci]

// ---------------- PTX helpers (sm_80 baseline only) ----------------
DEV_INLINE uint32_t smem_u32(const void* p) {
    uint32_t a;
    asm("{ .reg .u64 t; cvta.to.shared.u64 t, %1; cvt.u32.u64 %0, t; }"
        : "=r"(a) : "l"(p));
    return a;
}

DEV_INLINE void cp_async16(uint32_t dst, const void* src) {
    asm volatile("cp.async.ca.shared.global [%0], [%1], 16;"
                 :: "r"(dst), "l"(src) : "memory");
}
DEV_INLINE void cp_commit() {
    asm volatile("cp.async.commit_group;" ::: "memory");
}
template <int N> DEV_INLINE void cp_wait() {
    asm volatile("cp.async.wait_group %0;" :: "n"(N) : "memory");
}

// m16n8k16 fp16 MMA, fp32 accumulate
DEV_INLINE void mma_f16(float* c, const uint32_t* a, const uint32_t* b) {
    asm volatile(
        "mma.sync.aligned.m16n8k16.row.col.f32.f16.f16.f32 "
        "{%0,%1,%2,%3}, {%4,%5,%6,%7}, {%8,%9}, {%0,%1,%2,%3};"
        : "+f"(c[0]), "+f"(c[1]), "+f"(c[2]), "+f"(c[3])
        : "r"(a[0]), "r"(a[1]), "r"(a[2]), "r"(a[3]),
          "r"(b[0]), "r"(b[1]));
}

// ============================================================================
// Kernel 1: style[b][ci] = w[b,:] . affine_w[ci,:] + affine_b[ci]
// ============================================================================
__global__ void k_style(const float* __restrict__ w,
                        const float* __restrict__ aw,
                        const float* __restrict__ ab) {
    int gw = (blockIdx.x * blockDim.x + threadIdx.x) >> 5;
    int lane = threadIdx.x & 31;
    if (gw >= NB * CIN) return;
    int b = gw >> 9;
    int ci = gw & (CIN - 1);
    const float* wr = w + b * WDIM;
    const float* ar = aw + ci * WDIM;
    float s = 0.f;
    for (int d = lane; d < WDIM; d += 32) s += wr[d] * ar[d];
    #pragma unroll
    for (int o = 16; o; o >>= 1) s += __shfl_xor_sync(0xFFFFFFFFu, s, o);
    if (lane == 0) g_style[b * CIN + ci] = s + ab[ci];
}

// ============================================================================
// Kernel 2: g_wtap[tap][co][ci] = fp16(weight[co][ci][tap])
// ============================================================================
__global__ void k_wprep(const float* __restrict__ wt) {
    int idx = blockIdx.x * 256 + threadIdx.x;   // co*CIN + ci
    if (idx >= COUT * CIN) return;
    const float* src = wt + (size_t)idx * 9;
    #pragma unroll
    for (int tp = 0; tp < 9; tp++)
        g_wtap[tp * (COUT * CIN) + idx] = __float2half_rn(src[tp]);
}

// ============================================================================
// Kernel 3: zero margins + zero-padding borders of g_xpad (1 KB per row)
// ============================================================================
__global__ void k_zero() {
    int row = (int)blockIdx.x - XMARG;
    bool z;
    if (row < 0 || row >= GPT) z = true;
    else {
        int rem = row % PLANE;
        int py = rem / WP, px = rem % WP;
        z = (py == 0) || (py == WP - 1) || (px == 0) || (px == WP - 1);
    }
    if (!z) return;
    uint2* dst = (uint2*)(g_xpad + (size_t)(row + XMARG) * CIN);
    dst[threadIdx.x] = make_uint2(0u, 0u);
}

// ============================================================================
// Kernel 4: g_xpad[gp][ci] = fp16( x[b,ci,py-1,px-1] * style[b,ci] )
// ============================================================================
__global__ void k_xprep(const float* __restrict__ x) {
    __shared__ float tile[32 * 65];
    __shared__ float sstyle[32];
    int cib = blockIdx.x * 32;
    int py  = blockIdx.y + 1;          // padded row 1..64
    int b   = blockIdx.z;
    int t   = threadIdx.x;
    if (t < 32) sstyle[t] = g_style[b * CIN + cib + t];
    int i = t >> 3, j = t & 7;
    const float* srow = x + (((size_t)(b * CIN + cib + i) * RES + (py - 1)) * RES);
    float4 v0 = ((const float4*)srow)[j * 2];
    float4 v1 = ((const float4*)srow)[j * 2 + 1];
    int c = j * 8;
    tile[i * 65 + c + 0] = v0.x; tile[i * 65 + c + 1] = v0.y;
    tile[i * 65 + c + 2] = v0.z; tile[i * 65 + c + 3] = v0.w;
    tile[i * 65 + c + 4] = v1.x; tile[i * 65 + c + 5] = v1.y;
    tile[i * 65 + c + 6] = v1.z; tile[i * 65 + c + 7] = v1.w;
    __syncthreads();
    int wrp = t >> 5, l = t & 31;
    float st = sstyle[l];
    size_t rowbase = (size_t)XMARG + (size_t)b * PLANE + (size_t)py * WP;
    #pragma unroll
    for (int pp = 0; pp < 8; pp++) {
        int px = wrp * 8 + pp;
        float v = tile[l * 65 + px] * st;
        g_xpad[(rowbase + px + 1) * CIN + cib + l] = __float2half_rn(v);
    }
}

// ============================================================================
// Kernel 5: implicit-GEMM conv, mma.sync fp16, warp tile 64x64.
// BM=128 x BN=128, 128 threads (4 warps 2m x 2n), 2 CTAs/SM.
// 64x64 warp tile cuts smem-crossbar bytes/MAC from 0.094 to 0.061.
// ============================================================================
__global__ __launch_bounds__(NTHR, 2) void k_gemm(const float* __restrict__ bias,
                                                  float* __restrict__ out) {
    extern __shared__ __align__(128) char smem[];
    const int t = threadIdx.x;
    const int wid = t >> 5;
    const int lane = t & 31;
    const int g = lane >> 2;          // 0..7
    const int tg = lane & 3;          // 0..3
    const int wm = wid >> 1;          // 0..1  (m warp coord, 64 rows each)
    const int wn = wid & 1;           // 0..1  (n warp coord, 64 cols each)
    const int n0 = blockIdx.x * BN;
    const int gp0 = (int)blockIdx.y * BM;

    uint32_t sbase = smem_u32(smem);

    float c[4][8][4];
    #pragma unroll
    for (int mi = 0; mi < 4; mi++)
        #pragma unroll
        for (int ni = 0; ni < 8; ni++)
            #pragma unroll
            for (int q = 0; q < 4; q++) c[mi][ni][q] = 0.f;

    const __half* xsrc = g_xpad + (size_t)(XMARG + gp0 - 67) * CIN;

    // per-thread frag base offsets (in 32-bit words)
    const int a_off = (wm * 64 + g) * SRW + tg;
    const int b_off = (wn * 64 + g) * SRW + tg;

    auto issue_strip = [&](int kc) {
        const __half* src = xsrc + kc * KC;
        uint32_t dst = sbase + ((kc & 1) ? SO_S1 : SO_S0);
        #pragma unroll
        for (int k = 0; k < 9; k++) {
            int idx = t + k * NTHR;            // 262 rows x 4 chunks = 1048
            if (idx < STRIP_ROWS * 4) {
                int r = idx >> 2, j = idx & 3;
                cp_async16(dst + r * SRB + j * 16,
                           src + (size_t)r * CIN + j * 8);
            }
        }
        cp_commit();
    };
    auto issue_b = [&](int it) {
        int kc = it / 9, tap = it - kc * 9;
        const __half* wsrc = g_wtap + ((size_t)tap * COUT + n0) * CIN + kc * KC;
        uint32_t dst = sbase + ((it & 1) ? SO_B1 : SO_B0);
        #pragma unroll
        for (int k = 0; k < 4; k++) {
            int idx = t + k * NTHR;            // 128 rows x 4 chunks = 512
            int r = idx >> 2, j = idx & 3;
            cp_async16(dst + r * SRB + j * 16,
                       wsrc + (size_t)r * CIN + j * 8);
        }
        cp_commit();
    };

    // ---- prologue: groups S(0), B(0) ----
    issue_strip(0);
    issue_b(0);

    for (int it = 0; it < NIT; it++) {
        const int kc = it / 9;
        const int tap = it - kc * 9;

        // Outstanding (oldest->newest):
        //   tap==8: [B(it), S(kc+1)] -> wait<1>;  else [.., B(it)] -> wait<0>
        if (tap == 8 && kc + 1 < NCH) cp_wait<1>(); else cp_wait<0>();
        __syncthreads();

        if (it + 1 < NIT) issue_b(it + 1);                 // buffer (it+1)&1
        if (tap == 7 && kc + 1 < NCH) issue_strip(kc + 1); // buffer (kc+1)&1

        // ---- compute: tap shift is a pure strip-row offset ----
        const int srow0 = (tap / 3) * WP + (tap % 3);
        const uint32_t* ab =
            (const uint32_t*)(smem + ((kc & 1) ? SO_S1 : SO_S0)) +
            srow0 * SRW + a_off;
        const uint32_t* bb =
            (const uint32_t*)(smem + ((it & 1) ? SO_B1 : SO_B0)) + b_off;

        #pragma unroll
        for (int ks = 0; ks < 2; ks++) {       // K = 2 x 16
            uint32_t A[4][4];
            #pragma unroll
            for (int mi = 0; mi < 4; mi++) {
                const uint32_t* ap = ab + mi * (16 * SRW) + ks * 8;
                A[mi][0] = ap[0];
                A[mi][1] = ap[8 * SRW];
                A[mi][2] = ap[4];
                A[mi][3] = ap[8 * SRW + 4];
            }
            uint32_t B[8][2];
            #pragma unroll
            for (int ni = 0; ni < 8; ni++) {
                const uint32_t* bp = bb + ni * (8 * SRW) + ks * 8;
                B[ni][0] = bp[0];
                B[ni][1] = bp[4];
            }
            #pragma unroll
            for (int mi = 0; mi < 4; mi++)
                #pragma unroll
                for (int ni = 0; ni < 8; ni++)
                    mma_f16(c[mi][ni], A[mi], B[ni]);
        }
    }

    // ---- epilogue: c[mi][ni] rows (g, g+8), cols (2tg, 2tg+1) ----
    #pragma unroll
    for (int mi = 0; mi < 4; mi++) {
        #pragma unroll
        for (int half = 0; half < 2; half++) {
            int mloc = wm * 64 + mi * 16 + half * 8 + g;
            int gp = gp0 + mloc;
            if (gp >= GPT) continue;
            int b = gp / PLANE;
            int rem = gp - b * PLANE;
            int py = rem / WP, px = rem - py * WP;
            if (py < 1 || py > RES || px < 1 || px > RES) continue;
            size_t obase =
                (((size_t)b * COUT) * RES + (py - 1)) * RES + (px - 1);
            #pragma unroll
            for (int ni = 0; ni < 8; ni++) {
                #pragma unroll
                for (int j = 0; j < 2; j++) {
                    int co = n0 + wn * 64 + ni * 8 + 2 * tg + j;
                    out[obase + (size_t)co * (RES * RES)] =
                        c[mi][ni][half * 2 + j] + __ldg(&bias[co]);
                }
            }
        }
    }
}

// ============================================================================
// launch
// ============================================================================
extern "C" void kernel_launch(void* const* d_in, const int* in_sizes, int n_in,
                              void* d_out, int out_size) {
    const float* x   = (const float*)d_in[0];
    const float* w   = (const float*)d_in[1];
    const float* wt  = (const float*)d_in[2];
    const float* bia = (const float*)d_in[3];
    const float* aw  = (const float*)d_in[4];
    const float* ab  = (const float*)d_in[5];
    float* out = (float*)d_out;

    cudaFuncSetAttribute(k_gemm, cudaFuncAttributeMaxDynamicSharedMemorySize,
                         SMEM_TOTAL);

    k_style<<<(NB * CIN * 32 + 255) / 256, 256>>>(w, aw, ab);
    k_wprep<<<(COUT * CIN + 255) / 256, 256>>>(wt);
    k_zero<<<XROWS, 128>>>();
    k_xprep<<<dim3(CIN / 32, RES, NB), 256>>>(x);
    k_gemm<<<dim3(NT, MT), NTHR, SMEM_TOTAL>>>(bia, out);
}

// round 12
// speedup vs baseline: 2.2678x; 1.1896x over previous
#include <cuda_runtime.h>
#include <cuda_fp16.h>
#include <cstdint>
#include <cstddef>

#define DEV_INLINE __device__ __forceinline__

// ---------------- problem constants ----------------
constexpr int NB = 8, CIN = 512, COUT = 512, RES = 64, WDIM = 512;
constexpr int WP = 66;                 // padded spatial dim
constexpr int PLANE = WP * WP;         // 4356
constexpr int GPT = NB * PLANE;        // 34848 padded pixels total
constexpr int XMARG = 256;             // margin rows each side of g_xpad
constexpr int XROWS = GPT + 2 * XMARG; // 35360

// ---------------- GEMM tiling ----------------
constexpr int BM = 128, BN = 128, KC = 32;   // 32 ci per chunk
constexpr int NCH = CIN / KC;           // 16 ci-chunks
constexpr int MT = (GPT + BM - 1) / BM; // 273
constexpr int NT = COUT / BN;           // 4
constexpr int NIT = NCH * 9;            // 144 (kc,tap) iterations
constexpr int STRIP_ROWS = BM + 134;    // 262
constexpr int NTHR = 128;               // 4 warps, each 64x64

// fp16 rows: 32 ci = 64 B data, padded to 80 B (20 words) -> conflict-free
// (8 consecutive rows hit banks {0,20,8,28,16,4,24,12} per LDSM phase)
constexpr int SRW = 20;                 // strip/B row stride in 32-bit words
constexpr int SRB = SRW * 4;            // 80 bytes

// ---------------- smem layout (bytes) ----------------
constexpr int STRIP_BYTES = STRIP_ROWS * SRB;   // 20960
constexpr int BBYTES = 128 * SRB;               // 10240
constexpr int SO_S0 = 0;
constexpr int SO_S1 = 20992;
constexpr int SO_B0 = 41984;
constexpr int SO_B1 = 52224;
constexpr int SMEM_TOTAL = SO_B1 + BBYTES;      // 62464

// ---------------- device scratch (allocation is forbidden) ----------------
__device__ __align__(128) float  g_style[NB * CIN];
__device__ __align__(128) __half g_xpad[(size_t)XROWS * CIN];  // [row][ci]
__device__ __align__(128) __half g_wtap[9 * COUT * CIN];       // [tap][co][ci]

// ---------------- PTX helpers (sm_80 baseline only) ----------------
DEV_INLINE uint32_t smem_u32(const void* p) {
    uint32_t a;
    asm("{ .reg .u64 t; cvta.to.shared.u64 t, %1; cvt.u32.u64 %0, t; }"
        : "=r"(a) : "l"(p));
    return a;
}

DEV_INLINE void cp_async16(uint32_t dst, const void* src) {
    asm volatile("cp.async.ca.shared.global [%0], [%1], 16;"
                 :: "r"(dst), "l"(src) : "memory");
}
DEV_INLINE void cp_commit() {
    asm volatile("cp.async.commit_group;" ::: "memory");
}
template <int N> DEV_INLINE void cp_wait() {
    asm volatile("cp.async.wait_group %0;" :: "n"(N) : "memory");
}

DEV_INLINE void ldsm_x4(uint32_t& r0, uint32_t& r1, uint32_t& r2, uint32_t& r3,
                        uint32_t addr) {
    asm volatile("ldmatrix.sync.aligned.m8n8.x4.shared.b16 {%0,%1,%2,%3}, [%4];"
                 : "=r"(r0), "=r"(r1), "=r"(r2), "=r"(r3) : "r"(addr));
}

// m16n8k16 fp16 MMA, fp32 accumulate
DEV_INLINE void mma_f16(float* c, const uint32_t* a, const uint32_t* b) {
    asm volatile(
        "mma.sync.aligned.m16n8k16.row.col.f32.f16.f16.f32 "
        "{%0,%1,%2,%3}, {%4,%5,%6,%7}, {%8,%9}, {%0,%1,%2,%3};"
        : "+f"(c[0]), "+f"(c[1]), "+f"(c[2]), "+f"(c[3])
        : "r"(a[0]), "r"(a[1]), "r"(a[2]), "r"(a[3]),
          "r"(b[0]), "r"(b[1]));
}

// ============================================================================
// Kernel 1: style[b][ci] = w[b,:] . affine_w[ci,:] + affine_b[ci]
// ============================================================================
__global__ void k_style(const float* __restrict__ w,
                        const float* __restrict__ aw,
                        const float* __restrict__ ab) {
    int gw = (blockIdx.x * blockDim.x + threadIdx.x) >> 5;
    int lane = threadIdx.x & 31;
    if (gw >= NB * CIN) return;
    int b = gw >> 9;
    int ci = gw & (CIN - 1);
    const float* wr = w + b * WDIM;
    const float* ar = aw + ci * WDIM;
    float s = 0.f;
    for (int d = lane; d < WDIM; d += 32) s += wr[d] * ar[d];
    #pragma unroll
    for (int o = 16; o; o >>= 1) s += __shfl_xor_sync(0xFFFFFFFFu, s, o);
    if (lane == 0) g_style[b * CIN + ci] = s + ab[ci];
}

// ============================================================================
// Kernel 2: g_wtap[tap][co][ci] = fp16(weight[co][ci][tap])
// ============================================================================
__global__ void k_wprep(const float* __restrict__ wt) {
    int idx = blockIdx.x * 256 + threadIdx.x;   // co*CIN + ci
    if (idx >= COUT * CIN) return;
    const float* src = wt + (size_t)idx * 9;
    #pragma unroll
    for (int tp = 0; tp < 9; tp++)
        g_wtap[tp * (COUT * CIN) + idx] = __float2half_rn(src[tp]);
}

// ============================================================================
// Kernel 3: zero margins + zero-padding borders of g_xpad (1 KB per row)
// ============================================================================
__global__ void k_zero() {
    int row = (int)blockIdx.x - XMARG;
    bool z;
    if (row < 0 || row >= GPT) z = true;
    else {
        int rem = row % PLANE;
        int py = rem / WP, px = rem % WP;
        z = (py == 0) || (py == WP - 1) || (px == 0) || (px == WP - 1);
    }
    if (!z) return;
    uint2* dst = (uint2*)(g_xpad + (size_t)(row + XMARG) * CIN);
    dst[threadIdx.x] = make_uint2(0u, 0u);
}

// ============================================================================
// Kernel 4: g_xpad[gp][ci] = fp16( x[b,ci,py-1,px-1] * style[b,ci] )
// ============================================================================
__global__ void k_xprep(const float* __restrict__ x) {
    __shared__ float tile[32 * 65];
    __shared__ float sstyle[32];
    int cib = blockIdx.x * 32;
    int py  = blockIdx.y + 1;          // padded row 1..64
    int b   = blockIdx.z;
    int t   = threadIdx.x;
    if (t < 32) sstyle[t] = g_style[b * CIN + cib + t];
    int i = t >> 3, j = t & 7;
    const float* srow = x + (((size_t)(b * CIN + cib + i) * RES + (py - 1)) * RES);
    float4 v0 = ((const float4*)srow)[j * 2];
    float4 v1 = ((const float4*)srow)[j * 2 + 1];
    int c = j * 8;
    tile[i * 65 + c + 0] = v0.x; tile[i * 65 + c + 1] = v0.y;
    tile[i * 65 + c + 2] = v0.z; tile[i * 65 + c + 3] = v0.w;
    tile[i * 65 + c + 4] = v1.x; tile[i * 65 + c + 5] = v1.y;
    tile[i * 65 + c + 6] = v1.z; tile[i * 65 + c + 7] = v1.w;
    __syncthreads();
    int wrp = t >> 5, l = t & 31;
    float st = sstyle[l];
    size_t rowbase = (size_t)XMARG + (size_t)b * PLANE + (size_t)py * WP;
    #pragma unroll
    for (int pp = 0; pp < 8; pp++) {
        int px = wrp * 8 + pp;
        float v = tile[l * 65 + px] * st;
        g_xpad[(rowbase + px + 1) * CIN + cib + l] = __float2half_rn(v);
    }
}

// ============================================================================
// Kernel 5: implicit-GEMM conv, mma.sync fp16 + ldmatrix.x4 fragments.
// BM=128 x BN=128, 128 threads (4 warps 2m x 2n, 64x64 each), 2 CTAs/SM.
// LDSM cuts fragment-load instructions 4x (64 LDS -> 16 LDSM per warp-iter).
// ============================================================================
__global__ __launch_bounds__(NTHR, 2) void k_gemm(const float* __restrict__ bias,
                                                  float* __restrict__ out) {
    extern __shared__ __align__(128) char smem[];
    const int t = threadIdx.x;
    const int wid = t >> 5;
    const int lane = t & 31;
    const int g = lane >> 2;          // 0..7
    const int tg = lane & 3;          // 0..3
    const int wm = wid >> 1;          // 0..1  (m warp coord, 64 rows each)
    const int wn = wid & 1;           // 0..1  (n warp coord, 64 cols each)
    const int n0 = blockIdx.x * BN;
    const int gp0 = (int)blockIdx.y * BM;

    uint32_t sbase = smem_u32(smem);

    float c[4][8][4];
    #pragma unroll
    for (int mi = 0; mi < 4; mi++)
        #pragma unroll
        for (int ni = 0; ni < 8; ni++)
            #pragma unroll
            for (int q = 0; q < 4; q++) c[mi][ni][q] = 0.f;

    const __half* xsrc = g_xpad + (size_t)(XMARG + gp0 - 67) * CIN;

    // per-lane LDSM byte offsets (within a tile buffer)
    //  A mats (per mi): (m0-7,k0-7),(m8-15,k0-7),(m0-7,k8-15),(m8-15,k8-15)
    const uint32_t a_lsm = (uint32_t)((wm * 64 + (lane & 15)) * SRB +
                                      (lane >> 4) * 16);
    //  B mats (per npair): (n0-7,k0-7),(n0-7,k8-15),(n8-15,k0-7),(n8-15,k8-15)
    const uint32_t b_lsm = (uint32_t)((wn * 64 + (lane & 7) +
                                       ((lane >> 4) * 8)) * SRB +
                                      ((lane >> 3) & 1) * 16);

    auto issue_strip = [&](int kc) {
        const __half* src = xsrc + kc * KC;
        uint32_t dst = sbase + ((kc & 1) ? SO_S1 : SO_S0);
        #pragma unroll
        for (int k = 0; k < 9; k++) {
            int idx = t + k * NTHR;            // 262 rows x 4 chunks = 1048
            if (idx < STRIP_ROWS * 4) {
                int r = idx >> 2, j = idx & 3;
                cp_async16(dst + r * SRB + j * 16,
                           src + (size_t)r * CIN + j * 8);
            }
        }
        cp_commit();
    };
    auto issue_b = [&](int it) {
        int kc = it / 9, tap = it - kc * 9;
        const __half* wsrc = g_wtap + ((size_t)tap * COUT + n0) * CIN + kc * KC;
        uint32_t dst = sbase + ((it & 1) ? SO_B1 : SO_B0);
        #pragma unroll
        for (int k = 0; k < 4; k++) {
            int idx = t + k * NTHR;            // 128 rows x 4 chunks = 512
            int r = idx >> 2, j = idx & 3;
            cp_async16(dst + r * SRB + j * 16,
                       wsrc + (size_t)r * CIN + j * 8);
        }
        cp_commit();
    };

    // ---- prologue: groups S(0), B(0) ----
    issue_strip(0);
    issue_b(0);

    for (int it = 0; it < NIT; it++) {
        const int kc = it / 9;
        const int tap = it - kc * 9;

        // Outstanding (oldest->newest):
        //   tap==8: [B(it), S(kc+1)] -> wait<1>;  else [.., B(it)] -> wait<0>
        if (tap == 8 && kc + 1 < NCH) cp_wait<1>(); else cp_wait<0>();
        __syncthreads();

        if (it + 1 < NIT) issue_b(it + 1);                 // buffer (it+1)&1
        if (tap == 7 && kc + 1 < NCH) issue_strip(kc + 1); // buffer (kc+1)&1

        // ---- compute: tap shift is a pure strip-row offset ----
        const int srow0 = (tap / 3) * WP + (tap % 3);
        const uint32_t a_base = sbase + ((kc & 1) ? SO_S1 : SO_S0) +
                                (uint32_t)srow0 * SRB + a_lsm;
        const uint32_t b_base = sbase + ((it & 1) ? SO_B1 : SO_B0) + b_lsm;

        #pragma unroll
        for (int ks = 0; ks < 2; ks++) {       // K = 2 x 16
            uint32_t A[4][4];
            #pragma unroll
            for (int mi = 0; mi < 4; mi++)
                ldsm_x4(A[mi][0], A[mi][1], A[mi][2], A[mi][3],
                        a_base + mi * (16 * SRB) + ks * 32);
            uint32_t B[8][2];
            #pragma unroll
            for (int np = 0; np < 4; np++)
                ldsm_x4(B[2 * np][0], B[2 * np][1],
                        B[2 * np + 1][0], B[2 * np + 1][1],
                        b_base + np * (16 * SRB) + ks * 32);
            #pragma unroll
            for (int mi = 0; mi < 4; mi++)
                #pragma unroll
                for (int ni = 0; ni < 8; ni++)
                    mma_f16(c[mi][ni], A[mi], B[ni]);
        }
    }

    // ---- epilogue: c[mi][ni] rows (g, g+8), cols (2tg, 2tg+1) ----
    #pragma unroll
    for (int mi = 0; mi < 4; mi++) {
        #pragma unroll
        for (int half = 0; half < 2; half++) {
            int mloc = wm * 64 + mi * 16 + half * 8 + g;
            int gp = gp0 + mloc;
            if (gp >= GPT) continue;
            int b = gp / PLANE;
            int rem = gp - b * PLANE;
            int py = rem / WP, px = rem - py * WP;
            if (py < 1 || py > RES || px < 1 || px > RES) continue;
            size_t obase =
                (((size_t)b * COUT) * RES + (py - 1)) * RES + (px - 1);
            #pragma unroll
            for (int ni = 0; ni < 8; ni++) {
                #pragma unroll
                for (int j = 0; j < 2; j++) {
                    int co = n0 + wn * 64 + ni * 8 + 2 * tg + j;
                    out[obase + (size_t)co * (RES * RES)] =
                        c[mi][ni][half * 2 + j] + __ldg(&bias[co]);
                }
            }
        }
    }
}

// ============================================================================
// launch
// ============================================================================
extern "C" void kernel_launch(void* const* d_in, const int* in_sizes, int n_in,
                              void* d_out, int out_size) {
    const float* x   = (const float*)d_in[0];
    const float* w   = (const float*)d_in[1];
    const float* wt  = (const float*)d_in[2];
    const float* bia = (const float*)d_in[3];
    const float* aw  = (const float*)d_in[4];
    const float* ab  = (const float*)d_in[5];
    float* out = (float*)d_out;

    cudaFuncSetAttribute(k_gemm, cudaFuncAttributeMaxDynamicSharedMemorySize,
                         SMEM_TOTAL);

    k_style<<<(NB * CIN * 32 + 255) / 256, 256>>>(w, aw, ab);
    k_wprep<<<(COUT * CIN + 255) / 256, 256>>>(wt);
    k_zero<<<XROWS, 128>>>();
    k_xprep<<<dim3(CIN / 32, RES, NB), 256>>>(x);
    k_gemm<<<dim3(NT, MT), NTHR, SMEM_TOTAL>>>(bia, out);
}